// round 6
// baseline (speedup 1.0000x reference)
#include <cuda_runtime.h>
#include <cuda_bf16.h>
#include <math.h>

// Problem constants
#define BB 4
#define SS 4096
#define DD 1024
#define HH 16
#define DH 64
#define MM (BB * SS)          // 16384 rows
#define CC 64                 // chunk length
#define NC (SS / CC)          // 64 chunks per sequence
#define EPS 1e-6f

// ---------------------------------------------------------------------------
// Scratch (device globals; no allocation allowed)
// ---------------------------------------------------------------------------
__device__ float g_q[(size_t)MM * DD];
__device__ float g_k[(size_t)MM * DD];
__device__ float g_v[(size_t)MM * DD];
__device__ float g_attn[(size_t)MM * DD];
// chunk states: [B*H][NC][DH][DH]  (raw sums, then exclusive prefix in place)
__device__ float g_cS[(size_t)BB * HH * NC * DH * DH];
__device__ float g_cz[(size_t)BB * HH * NC * DH];

// ---------------------------------------------------------------------------
// fp32 tiled GEMM: C[M,1024] = A[M,1024] @ B[1024,1024]; mode 1 -> phi(elu+1)
// 128x128 tile, BK=8, 256 threads, 8x8 per thread (split 4+4 for LDS.128)
// ---------------------------------------------------------------------------
__global__ __launch_bounds__(256) void gemm128(const float* __restrict__ A,
                                               const float* __restrict__ B,
                                               float* __restrict__ C,
                                               int mode) {
    const int K = 1024, N = 1024;
    __shared__ float As[8][128];
    __shared__ float Bs[8][128];

    int tid  = threadIdx.x;
    int brow = blockIdx.y * 128;
    int bcol = blockIdx.x * 128;

    int arow = tid >> 1;           // 0..127
    int acol = (tid & 1) * 4;      // 0 or 4
    int brl  = tid >> 5;           // 0..7
    int bcl  = (tid & 31) * 4;     // 0..124

    const float* Aptr = A + (size_t)(brow + arow) * K + acol;
    const float* Bptr = B + (size_t)brl * N + bcol + bcl;

    int tx = tid & 15, ty = tid >> 4;

    float acc[8][8];
#pragma unroll
    for (int i = 0; i < 8; ++i)
#pragma unroll
        for (int j = 0; j < 8; ++j) acc[i][j] = 0.f;

    for (int k0 = 0; k0 < K; k0 += 8) {
        float4 a4 = *(const float4*)Aptr;  Aptr += 8;
        float4 b4 = *(const float4*)Bptr;  Bptr += (size_t)8 * N;
        As[acol + 0][arow] = a4.x;
        As[acol + 1][arow] = a4.y;
        As[acol + 2][arow] = a4.z;
        As[acol + 3][arow] = a4.w;
        *(float4*)&Bs[brl][bcl] = b4;
        __syncthreads();
#pragma unroll
        for (int kk = 0; kk < 8; ++kk) {
            float4 a0 = *(const float4*)&As[kk][ty * 4];
            float4 a1 = *(const float4*)&As[kk][64 + ty * 4];
            float4 b0 = *(const float4*)&Bs[kk][tx * 4];
            float4 b1 = *(const float4*)&Bs[kk][64 + tx * 4];
            float ar[8] = {a0.x, a0.y, a0.z, a0.w, a1.x, a1.y, a1.z, a1.w};
            float br[8] = {b0.x, b0.y, b0.z, b0.w, b1.x, b1.y, b1.z, b1.w};
#pragma unroll
            for (int i = 0; i < 8; ++i)
#pragma unroll
                for (int j = 0; j < 8; ++j) acc[i][j] += ar[i] * br[j];
        }
        __syncthreads();
    }

    // epilogue
#pragma unroll
    for (int i = 0; i < 8; ++i) {
        int r = (i < 4) ? (ty * 4 + i) : (64 + ty * 4 + i - 4);
        float vals[8];
#pragma unroll
        for (int j = 0; j < 8; ++j) {
            float v = acc[i][j];
            if (mode == 1) v = (v > 0.f) ? (v + 1.f) : expf(v);  // elu(v)+1
            vals[j] = v;
        }
        float* crow = C + (size_t)(brow + r) * N + bcol;
        *(float4*)&crow[tx * 4]      = make_float4(vals[0], vals[1], vals[2], vals[3]);
        *(float4*)&crow[64 + tx * 4] = make_float4(vals[4], vals[5], vals[6], vals[7]);
    }
}

// ---------------------------------------------------------------------------
// Per-chunk sums: cS[bid] = K_chunk^T @ V_chunk (64x64), cz[bid] = colsum(K)
// grid = B*H*NC blocks, 256 threads
// ---------------------------------------------------------------------------
__global__ __launch_bounds__(256) void chunk_sums(const float* __restrict__ k,
                                                  const float* __restrict__ v,
                                                  float* __restrict__ cS,
                                                  float* __restrict__ cz) {
    __shared__ float Ks[64 * 64];
    __shared__ float Vs[64 * 64];

    int bid = blockIdx.x;              // bh*NC + c
    int bh  = bid >> 6;
    int c   = bid & 63;
    int b   = bh >> 4;
    int tid = threadIdx.x;

    size_t gbase = ((size_t)(b * SS + c * CC)) * DD + (size_t)(bh & 15) * DH;
    for (int t4 = tid; t4 < 1024; t4 += 256) {   // 64 rows x 16 float4
        int row = t4 >> 4;
        int c4  = (t4 & 15) * 4;
        *(float4*)&Ks[row * 64 + c4] = *(const float4*)&k[gbase + (size_t)row * DD + c4];
        *(float4*)&Vs[row * 64 + c4] = *(const float4*)&v[gbase + (size_t)row * DD + c4];
    }
    __syncthreads();

    int d  = tid >> 2;
    int q4 = tid & 3;
    float acc[16];
#pragma unroll
    for (int ee = 0; ee < 16; ++ee) acc[ee] = 0.f;

    for (int t = 0; t < 64; ++t) {
        float kd = Ks[t * 64 + d];
#pragma unroll
        for (int ee = 0; ee < 16; ++ee)
            acc[ee] += kd * Vs[t * 64 + ee * 4 + q4];
    }
    float* out = cS + (size_t)bid * 4096 + d * 64;
#pragma unroll
    for (int ee = 0; ee < 16; ++ee) out[ee * 4 + q4] = acc[ee];

    if (tid < 64) {
        float zsum = 0.f;
        for (int t = 0; t < 64; ++t) zsum += Ks[t * 64 + tid];
        cz[(size_t)bid * 64 + tid] = zsum;
    }
}

// ---------------------------------------------------------------------------
// Exclusive prefix over chunks, seeded with state_cache. In-place on cS/cz.
// grid = B*H blocks, 256 threads (thread owns 16 of 4096 S entries; tid<64 own z)
// ---------------------------------------------------------------------------
__global__ __launch_bounds__(256) void prefix_kernel(const float* __restrict__ cache,
                                                     float* __restrict__ cS,
                                                     float* __restrict__ cz) {
    int bh  = blockIdx.x;
    int tid = threadIdx.x;

    float run[16];
    {
        int f0 = tid * 16;
#pragma unroll
        for (int u = 0; u < 16; ++u) {
            int f = f0 + u;
            int d = f >> 6, e = f & 63;
            run[u] = cache[((size_t)bh * 65 + d) * 64 + e];   // S0
        }
    }
    float runz = (tid < 64) ? cache[((size_t)bh * 65 + 64) * 64 + tid] : 0.f;  // z0

    for (int c = 0; c < NC; ++c) {
        size_t base = ((size_t)(bh * NC + c)) * 4096 + (size_t)tid * 16;
#pragma unroll
        for (int u = 0; u < 16; ++u) {
            float t = cS[base + u];
            cS[base + u] = run[u];
            run[u] += t;
        }
        if (tid < 64) {
            size_t zb = ((size_t)(bh * NC + c)) * 64 + tid;
            float t = cz[zb];
            cz[zb] = runz;
            runz += t;
        }
    }
}

// ---------------------------------------------------------------------------
// Intra-chunk causal attention + inter-chunk state application.
// out[i] = (Q_i @ S_start + sum_{j<=i} (Q_i.K_j) V_j) / (Q_i.z_start + rowsumA + eps)
// grid = B*H*NC blocks, 256 threads (thread = (row i, quarter q4), 16 cols each)
// ---------------------------------------------------------------------------
#define PSTR 68   // padded shared row stride (floats): 16B-aligned, conflict-free
#define SMEM_INTRA ((5 * 64 * PSTR + 64) * 4)

__global__ __launch_bounds__(256) void intra_kernel(const float* __restrict__ q,
                                                    const float* __restrict__ k,
                                                    const float* __restrict__ v,
                                                    const float* __restrict__ cS,
                                                    const float* __restrict__ cz,
                                                    float* __restrict__ outp) {
    extern __shared__ float sm[];
    float* Qs = sm;
    float* Ks = sm + 64 * PSTR;
    float* Vs = sm + 2 * 64 * PSTR;
    float* Ss = sm + 3 * 64 * PSTR;   // S_start, [d][e]
    float* As = sm + 4 * 64 * PSTR;   // masked A, [i][j]
    float* zs = sm + 5 * 64 * PSTR;   // z_start

    int bid = blockIdx.x;
    int bh  = bid >> 6;
    int c   = bid & 63;
    int b   = bh >> 4;
    int tid = threadIdx.x;

    size_t gbase = ((size_t)(b * SS + c * CC)) * DD + (size_t)(bh & 15) * DH;
    for (int t4 = tid; t4 < 1024; t4 += 256) {
        int row = t4 >> 4;
        int c4  = (t4 & 15) * 4;
        size_t go = gbase + (size_t)row * DD + c4;
        *(float4*)&Qs[row * PSTR + c4] = *(const float4*)&q[go];
        *(float4*)&Ks[row * PSTR + c4] = *(const float4*)&k[go];
        *(float4*)&Vs[row * PSTR + c4] = *(const float4*)&v[go];
        *(float4*)&Ss[row * PSTR + c4] = *(const float4*)&cS[(size_t)bid * 4096 + (size_t)t4 * 4];
    }
    if (tid < 64) zs[tid] = cz[(size_t)bid * 64 + tid];
    __syncthreads();

    int i  = tid >> 2;         // chunk row
    int q4 = tid & 3;          // column-quarter (strided e = ee*4+q4, j = jj*4+q4)
    const float* qrow = &Qs[i * PSTR];

    // Phase A: masked A row strip + den
    float ap[16];
#pragma unroll
    for (int jj = 0; jj < 16; ++jj) ap[jj] = 0.f;
    for (int d = 0; d < 64; ++d) {
        float qd = qrow[d];
#pragma unroll
        for (int jj = 0; jj < 16; ++jj)
            ap[jj] += qd * Ks[(jj * 4 + q4) * PSTR + d];
    }
    float den = 0.f;
#pragma unroll
    for (int jj = 0; jj < 16; ++jj) {
        int j = jj * 4 + q4;
        if (j > i) ap[jj] = 0.f;     // causal mask (inclusive diagonal)
        As[i * PSTR + j] = ap[jj];
        den += ap[jj];
    }
#pragma unroll
    for (int dd = 0; dd < 16; ++dd) {
        int d = dd * 4 + q4;
        den += qrow[d] * zs[d];
    }
    den += __shfl_xor_sync(0xffffffffu, den, 1);
    den += __shfl_xor_sync(0xffffffffu, den, 2);
    float inv = 1.f / (den + EPS);
    __syncthreads();

    // Phase B: num = Q @ S_start + A @ V
    float num[16];
#pragma unroll
    for (int ee = 0; ee < 16; ++ee) num[ee] = 0.f;
    for (int d = 0; d < 64; ++d) {
        float qd = qrow[d];
#pragma unroll
        for (int ee = 0; ee < 16; ++ee)
            num[ee] += qd * Ss[d * PSTR + ee * 4 + q4];
    }
    for (int j = 0; j < 64; ++j) {
        float aij = As[i * PSTR + j];
#pragma unroll
        for (int ee = 0; ee < 16; ++ee)
            num[ee] += aij * Vs[j * PSTR + ee * 4 + q4];
    }

    float* orow = outp + gbase + (size_t)i * DD;
#pragma unroll
    for (int ee = 0; ee < 16; ++ee)
        orow[ee * 4 + q4] = num[ee] * inv;
}

// ---------------------------------------------------------------------------
// Launch
// ---------------------------------------------------------------------------
extern "C" void kernel_launch(void* const* d_in, const int* in_sizes, int n_in,
                              void* d_out, int out_size) {
    const float* x     = (const float*)d_in[0];
    const float* cache = (const float*)d_in[1];
    const float* Wq    = (const float*)d_in[2];
    const float* Wk    = (const float*)d_in[3];
    const float* Wv    = (const float*)d_in[4];
    const float* Wo    = (const float*)d_in[5];
    float* out = (float*)d_out;

    float *qp, *kp, *vp, *ap, *cSp, *czp;
    cudaGetSymbolAddress((void**)&qp,  g_q);
    cudaGetSymbolAddress((void**)&kp,  g_k);
    cudaGetSymbolAddress((void**)&vp,  g_v);
    cudaGetSymbolAddress((void**)&ap,  g_attn);
    cudaGetSymbolAddress((void**)&cSp, g_cS);
    cudaGetSymbolAddress((void**)&czp, g_cz);

    cudaFuncSetAttribute(intra_kernel, cudaFuncAttributeMaxDynamicSharedMemorySize,
                         SMEM_INTRA);

    dim3 gg(DD / 128, MM / 128);   // (8, 128)
    gemm128<<<gg, 256>>>(x, Wq, qp, 1);
    gemm128<<<gg, 256>>>(x, Wk, kp, 1);
    gemm128<<<gg, 256>>>(x, Wv, vp, 0);
    chunk_sums<<<BB * HH * NC, 256>>>(kp, vp, cSp, czp);
    prefix_kernel<<<BB * HH, 256>>>(cache, cSp, czp);
    intra_kernel<<<BB * HH * NC, 256, SMEM_INTRA>>>(qp, kp, vp, cSp, czp, ap);
    gemm128<<<gg, 256>>>(ap, Wo, out, 0);
}

// round 7
// speedup vs baseline: 1.0461x; 1.0461x over previous
#include <cuda_runtime.h>
#include <cuda_bf16.h>
#include <math.h>

// Problem constants
#define BB 4
#define SS 4096
#define DD 1024
#define HH 16
#define DH 64
#define MM (BB * SS)          // 16384 rows
#define CC 64                 // chunk length
#define NC (SS / CC)          // 64 chunks per sequence
#define EPS 1e-6f

// ---------------------------------------------------------------------------
// Scratch (device globals; no allocation allowed)
// ---------------------------------------------------------------------------
__device__ float g_q[(size_t)MM * DD];
__device__ float g_k[(size_t)MM * DD];
__device__ float g_v[(size_t)MM * DD];
__device__ float g_attn[(size_t)MM * DD];
// chunk states: [B*H][NC][DH][DH]  (raw sums, then exclusive prefix in place)
__device__ float g_cS[(size_t)BB * HH * NC * DH * DH];
__device__ float g_cz[(size_t)BB * HH * NC * DH];

// ---------------------------------------------------------------------------
// fp32 tiled GEMM: C[M,1024] = A[M,1024] @ B[1024,1024]; mode 1 -> phi(elu+1)
// 128x128 tile, BK=8, 256 threads, 8x8 per thread (split 4+4 for LDS.128)
// ---------------------------------------------------------------------------
__global__ __launch_bounds__(256) void gemm128(const float* __restrict__ A,
                                               const float* __restrict__ B,
                                               float* __restrict__ C,
                                               int mode) {
    const int K = 1024, N = 1024;
    __shared__ float As[8][128];
    __shared__ float Bs[8][128];

    int tid  = threadIdx.x;
    int brow = blockIdx.y * 128;
    int bcol = blockIdx.x * 128;

    int arow = tid >> 1;           // 0..127
    int acol = (tid & 1) * 4;      // 0 or 4
    int brl  = tid >> 5;           // 0..7
    int bcl  = (tid & 31) * 4;     // 0..124

    const float* Aptr = A + (size_t)(brow + arow) * K + acol;
    const float* Bptr = B + (size_t)brl * N + bcol + bcl;

    int tx = tid & 15, ty = tid >> 4;

    float acc[8][8];
#pragma unroll
    for (int i = 0; i < 8; ++i)
#pragma unroll
        for (int j = 0; j < 8; ++j) acc[i][j] = 0.f;

    for (int k0 = 0; k0 < K; k0 += 8) {
        float4 a4 = *(const float4*)Aptr;  Aptr += 8;
        float4 b4 = *(const float4*)Bptr;  Bptr += (size_t)8 * N;
        As[acol + 0][arow] = a4.x;
        As[acol + 1][arow] = a4.y;
        As[acol + 2][arow] = a4.z;
        As[acol + 3][arow] = a4.w;
        *(float4*)&Bs[brl][bcl] = b4;
        __syncthreads();
#pragma unroll
        for (int kk = 0; kk < 8; ++kk) {
            float4 a0 = *(const float4*)&As[kk][ty * 4];
            float4 a1 = *(const float4*)&As[kk][64 + ty * 4];
            float4 b0 = *(const float4*)&Bs[kk][tx * 4];
            float4 b1 = *(const float4*)&Bs[kk][64 + tx * 4];
            float ar[8] = {a0.x, a0.y, a0.z, a0.w, a1.x, a1.y, a1.z, a1.w};
            float br[8] = {b0.x, b0.y, b0.z, b0.w, b1.x, b1.y, b1.z, b1.w};
#pragma unroll
            for (int i = 0; i < 8; ++i)
#pragma unroll
                for (int j = 0; j < 8; ++j) acc[i][j] += ar[i] * br[j];
        }
        __syncthreads();
    }

    // epilogue
#pragma unroll
    for (int i = 0; i < 8; ++i) {
        int r = (i < 4) ? (ty * 4 + i) : (64 + ty * 4 + i - 4);
        float vals[8];
#pragma unroll
        for (int j = 0; j < 8; ++j) {
            float v = acc[i][j];
            if (mode == 1) v = (v > 0.f) ? (v + 1.f) : expf(v);  // elu(v)+1
            vals[j] = v;
        }
        float* crow = C + (size_t)(brow + r) * N + bcol;
        *(float4*)&crow[tx * 4]      = make_float4(vals[0], vals[1], vals[2], vals[3]);
        *(float4*)&crow[64 + tx * 4] = make_float4(vals[4], vals[5], vals[6], vals[7]);
    }
}

// ---------------------------------------------------------------------------
// Per-chunk sums: cS[bid] = K_chunk^T @ V_chunk (64x64), cz[bid] = colsum(K)
// grid = B*H*NC blocks, 256 threads
// ---------------------------------------------------------------------------
__global__ __launch_bounds__(256) void chunk_sums(const float* __restrict__ k,
                                                  const float* __restrict__ v,
                                                  float* __restrict__ cS,
                                                  float* __restrict__ cz) {
    __shared__ float Ks[64 * 64];
    __shared__ float Vs[64 * 64];

    int bid = blockIdx.x;              // bh*NC + c
    int bh  = bid >> 6;
    int c   = bid & 63;
    int b   = bh >> 4;
    int tid = threadIdx.x;

    size_t gbase = ((size_t)(b * SS + c * CC)) * DD + (size_t)(bh & 15) * DH;
    for (int t4 = tid; t4 < 1024; t4 += 256) {   // 64 rows x 16 float4
        int row = t4 >> 4;
        int c4  = (t4 & 15) * 4;
        *(float4*)&Ks[row * 64 + c4] = *(const float4*)&k[gbase + (size_t)row * DD + c4];
        *(float4*)&Vs[row * 64 + c4] = *(const float4*)&v[gbase + (size_t)row * DD + c4];
    }
    __syncthreads();

    int d  = tid >> 2;
    int q4 = tid & 3;
    float acc[16];
#pragma unroll
    for (int ee = 0; ee < 16; ++ee) acc[ee] = 0.f;

    for (int t = 0; t < 64; ++t) {
        float kd = Ks[t * 64 + d];
#pragma unroll
        for (int ee = 0; ee < 16; ++ee)
            acc[ee] += kd * Vs[t * 64 + ee * 4 + q4];
    }
    float* out = cS + (size_t)bid * 4096 + d * 64;
#pragma unroll
    for (int ee = 0; ee < 16; ++ee) out[ee * 4 + q4] = acc[ee];

    if (tid < 64) {
        float zsum = 0.f;
        for (int t = 0; t < 64; ++t) zsum += Ks[t * 64 + tid];
        cz[(size_t)bid * 64 + tid] = zsum;
    }
}

// ---------------------------------------------------------------------------
// Exclusive prefix over chunks, seeded with state_cache. In-place on cS/cz.
// grid = B*H blocks, 256 threads (thread owns 16 of 4096 S entries; tid<64 own z)
// ---------------------------------------------------------------------------
__global__ __launch_bounds__(256) void prefix_kernel(const float* __restrict__ cache,
                                                     float* __restrict__ cS,
                                                     float* __restrict__ cz) {
    int bh  = blockIdx.x;
    int tid = threadIdx.x;

    float run[16];
    {
        int f0 = tid * 16;
#pragma unroll
        for (int u = 0; u < 16; ++u) {
            int f = f0 + u;
            int d = f >> 6, e = f & 63;
            run[u] = cache[((size_t)bh * 65 + d) * 64 + e];   // S0
        }
    }
    float runz = (tid < 64) ? cache[((size_t)bh * 65 + 64) * 64 + tid] : 0.f;  // z0

    for (int c = 0; c < NC; ++c) {
        size_t base = ((size_t)(bh * NC + c)) * 4096 + (size_t)tid * 16;
#pragma unroll
        for (int u = 0; u < 16; ++u) {
            float t = cS[base + u];
            cS[base + u] = run[u];
            run[u] += t;
        }
        if (tid < 64) {
            size_t zb = ((size_t)(bh * NC + c)) * 64 + tid;
            float t = cz[zb];
            cz[zb] = runz;
            runz += t;
        }
    }
}

// ---------------------------------------------------------------------------
// Intra-chunk causal attention + inter-chunk state application.
// out[i] = (Q_i @ S_start + sum_{j<=i} (Q_i.K_j) V_j) / (Q_i.z_start + rowsumA + eps)
// grid = B*H*NC blocks, 256 threads (thread = (row i, quarter q4), 16 cols each)
// ---------------------------------------------------------------------------
#define PSTR 68   // padded shared row stride (floats): 16B-aligned, conflict-free
#define SMEM_INTRA ((5 * 64 * PSTR + 64) * 4)

__global__ __launch_bounds__(256) void intra_kernel(const float* __restrict__ q,
                                                    const float* __restrict__ k,
                                                    const float* __restrict__ v,
                                                    const float* __restrict__ cS,
                                                    const float* __restrict__ cz,
                                                    float* __restrict__ outp) {
    extern __shared__ float sm[];
    float* Qs = sm;
    float* Ks = sm + 64 * PSTR;
    float* Vs = sm + 2 * 64 * PSTR;
    float* Ss = sm + 3 * 64 * PSTR;   // S_start, [d][e]
    float* As = sm + 4 * 64 * PSTR;   // masked A, [i][j]
    float* zs = sm + 5 * 64 * PSTR;   // z_start

    int bid = blockIdx.x;
    int bh  = bid >> 6;
    int c   = bid & 63;
    int b   = bh >> 4;
    int tid = threadIdx.x;

    size_t gbase = ((size_t)(b * SS + c * CC)) * DD + (size_t)(bh & 15) * DH;
    for (int t4 = tid; t4 < 1024; t4 += 256) {
        int row = t4 >> 4;
        int c4  = (t4 & 15) * 4;
        size_t go = gbase + (size_t)row * DD + c4;
        *(float4*)&Qs[row * PSTR + c4] = *(const float4*)&q[go];
        *(float4*)&Ks[row * PSTR + c4] = *(const float4*)&k[go];
        *(float4*)&Vs[row * PSTR + c4] = *(const float4*)&v[go];
        *(float4*)&Ss[row * PSTR + c4] = *(const float4*)&cS[(size_t)bid * 4096 + (size_t)t4 * 4];
    }
    if (tid < 64) zs[tid] = cz[(size_t)bid * 64 + tid];
    __syncthreads();

    int i  = tid >> 2;         // chunk row
    int q4 = tid & 3;          // column-quarter (strided e = ee*4+q4, j = jj*4+q4)
    const float* qrow = &Qs[i * PSTR];

    // Phase A: masked A row strip + den
    float ap[16];
#pragma unroll
    for (int jj = 0; jj < 16; ++jj) ap[jj] = 0.f;
    for (int d = 0; d < 64; ++d) {
        float qd = qrow[d];
#pragma unroll
        for (int jj = 0; jj < 16; ++jj)
            ap[jj] += qd * Ks[(jj * 4 + q4) * PSTR + d];
    }
    float den = 0.f;
#pragma unroll
    for (int jj = 0; jj < 16; ++jj) {
        int j = jj * 4 + q4;
        if (j > i) ap[jj] = 0.f;     // causal mask (inclusive diagonal)
        As[i * PSTR + j] = ap[jj];
        den += ap[jj];
    }
#pragma unroll
    for (int dd = 0; dd < 16; ++dd) {
        int d = dd * 4 + q4;
        den += qrow[d] * zs[d];
    }
    den += __shfl_xor_sync(0xffffffffu, den, 1);
    den += __shfl_xor_sync(0xffffffffu, den, 2);
    float inv = 1.f / (den + EPS);
    __syncthreads();

    // Phase B: num = Q @ S_start + A @ V
    float num[16];
#pragma unroll
    for (int ee = 0; ee < 16; ++ee) num[ee] = 0.f;
    for (int d = 0; d < 64; ++d) {
        float qd = qrow[d];
#pragma unroll
        for (int ee = 0; ee < 16; ++ee)
            num[ee] += qd * Ss[d * PSTR + ee * 4 + q4];
    }
    for (int j = 0; j < 64; ++j) {
        float aij = As[i * PSTR + j];
#pragma unroll
        for (int ee = 0; ee < 16; ++ee)
            num[ee] += aij * Vs[j * PSTR + ee * 4 + q4];
    }

    float* orow = outp + gbase + (size_t)i * DD;
#pragma unroll
    for (int ee = 0; ee < 16; ++ee)
        orow[ee * 4 + q4] = num[ee] * inv;
}

// ---------------------------------------------------------------------------
// Launch
// ---------------------------------------------------------------------------
extern "C" void kernel_launch(void* const* d_in, const int* in_sizes, int n_in,
                              void* d_out, int out_size) {
    const float* x     = (const float*)d_in[0];
    const float* cache = (const float*)d_in[1];
    const float* Wq    = (const float*)d_in[2];
    const float* Wk    = (const float*)d_in[3];
    const float* Wv    = (const float*)d_in[4];
    const float* Wo    = (const float*)d_in[5];
    float* out = (float*)d_out;

    float *qp, *kp, *vp, *ap, *cSp, *czp;
    cudaGetSymbolAddress((void**)&qp,  g_q);
    cudaGetSymbolAddress((void**)&kp,  g_k);
    cudaGetSymbolAddress((void**)&vp,  g_v);
    cudaGetSymbolAddress((void**)&ap,  g_attn);
    cudaGetSymbolAddress((void**)&cSp, g_cS);
    cudaGetSymbolAddress((void**)&czp, g_cz);

    cudaFuncSetAttribute(intra_kernel, cudaFuncAttributeMaxDynamicSharedMemorySize,
                         SMEM_INTRA);

    dim3 gg(DD / 128, MM / 128);   // (8, 128)
    gemm128<<<gg, 256>>>(x, Wq, qp, 1);
    gemm128<<<gg, 256>>>(x, Wk, kp, 1);
    gemm128<<<gg, 256>>>(x, Wv, vp, 0);
    chunk_sums<<<BB * HH * NC, 256>>>(kp, vp, cSp, czp);
    prefix_kernel<<<BB * HH, 256>>>(cache, cSp, czp);
    intra_kernel<<<BB * HH * NC, 256, SMEM_INTRA>>>(qp, kp, vp, cSp, czp, ap);
    gemm128<<<gg, 256>>>(ap, Wo, out, 0);
}

// round 9
// speedup vs baseline: 1.2780x; 1.2217x over previous
#include <cuda_runtime.h>
#include <cuda_bf16.h>
#include <math.h>
#include <cstdint>

// Problem constants
#define BB 4
#define SS 4096
#define DD 1024
#define HH 16
#define DH 64
#define MM (BB * SS)          // 16384 rows
#define CC 64                 // chunk length
#define NC (SS / CC)          // 64 chunks per sequence
#define EPS 1e-6f

// ---------------------------------------------------------------------------
// Scratch (device globals; no allocation allowed)
// ---------------------------------------------------------------------------
__device__ __align__(256) float g_q[(size_t)MM * DD];
__device__ __align__(256) float g_k[(size_t)MM * DD];
__device__ __align__(256) float g_v[(size_t)MM * DD];
__device__ __align__(256) __nv_bfloat16 g_xhi[(size_t)MM * DD];
__device__ __align__(256) __nv_bfloat16 g_xlo[(size_t)MM * DD];
__device__ __align__(256) __nv_bfloat16 g_ahi[(size_t)MM * DD];
__device__ __align__(256) __nv_bfloat16 g_alo[(size_t)MM * DD];
// transposed weights [N,K] bf16, hi/lo, 4 weights (q,k,v,o)
__device__ __align__(256) __nv_bfloat16 g_wthi[4][(size_t)DD * DD];
__device__ __align__(256) __nv_bfloat16 g_wtlo[4][(size_t)DD * DD];
// chunk states: [B*H][NC][DH][DH]
__device__ __align__(256) float g_cS[(size_t)BB * HH * NC * DH * DH];
__device__ __align__(256) float g_cz[(size_t)BB * HH * NC * DH];

// ---------------------------------------------------------------------------
// Warp-MMA helpers (sm_80-era PTX; assembles for sm_103)
// ---------------------------------------------------------------------------
__device__ __forceinline__ uint32_t smem_u32(const void* p) {
    uint32_t a;
    asm("{ .reg .u64 t; cvta.to.shared.u64 t, %1; cvt.u32.u64 %0, t; }"
        : "=r"(a) : "l"(p));
    return a;
}
__device__ __forceinline__ void ldsm_x4(uint32_t* r, uint32_t addr) {
    asm volatile("ldmatrix.sync.aligned.m8n8.x4.shared.b16 {%0,%1,%2,%3}, [%4];"
                 : "=r"(r[0]), "=r"(r[1]), "=r"(r[2]), "=r"(r[3]) : "r"(addr));
}
__device__ __forceinline__ void mma_bf16(float* d, const uint32_t* a,
                                         uint32_t b0, uint32_t b1) {
    asm volatile(
        "mma.sync.aligned.m16n8k16.row.col.f32.bf16.bf16.f32 "
        "{%0,%1,%2,%3}, {%4,%5,%6,%7}, {%8,%9}, {%0,%1,%2,%3};"
        : "+f"(d[0]), "+f"(d[1]), "+f"(d[2]), "+f"(d[3])
        : "r"(a[0]), "r"(a[1]), "r"(a[2]), "r"(a[3]), "r"(b0), "r"(b1));
}

// ---------------------------------------------------------------------------
// mma.sync bf16 GEMM with hi/lo split (3 accumulating passes):
// C[M,1024] = (Ahi+Alo)[M,K] @ (Bhi+Blo)[N,K]^T, fp32 out.
// CTA 128x128, BK=32, 8 warps (2x4), warp tile 64x32. mode 1 -> phi=elu+1.
// ---------------------------------------------------------------------------
#define GBK 32
#define NKCH (DD / GBK)   // 32
#define ASTR 40           // padded smem row stride (bf16 elems): conflict-free ldmatrix

__global__ __launch_bounds__(256, 1) void gemm_mma(const __nv_bfloat16* __restrict__ Ahi,
                                                   const __nv_bfloat16* __restrict__ Alo,
                                                   const __nv_bfloat16* __restrict__ Bhi,
                                                   const __nv_bfloat16* __restrict__ Blo,
                                                   float* __restrict__ C, int mode) {
    __shared__ __nv_bfloat16 sAh[128 * ASTR];
    __shared__ __nv_bfloat16 sAl[128 * ASTR];
    __shared__ __nv_bfloat16 sBh[128 * ASTR];
    __shared__ __nv_bfloat16 sBl[128 * ASTR];

    int tid  = threadIdx.x;
    int wid  = tid >> 5;
    int lane = tid & 31;
    int wr   = wid >> 2;      // 0..1  (M direction, 64 rows)
    int wc   = wid & 3;       // 0..3  (N direction, 32 cols)
    int m0   = blockIdx.y * 128;
    int n0   = blockIdx.x * 128;

    uint32_t bAh = smem_u32(sAh), bAl = smem_u32(sAl);
    uint32_t bBh = smem_u32(sBh), bBl = smem_u32(sBl);

    // per-thread load coords: 2 uint4 (8 bf16) chunks per tile per BK step
    int r0c = (tid + 0)   >> 2, c0c = ((tid + 0)   & 3) * 8;
    int r1c = (tid + 256) >> 2, c1c = ((tid + 256) & 3) * 8;

    float acc[4][4][4];
#pragma unroll
    for (int i = 0; i < 4; ++i)
#pragma unroll
        for (int j = 0; j < 4; ++j)
#pragma unroll
            for (int r = 0; r < 4; ++r) acc[i][j][r] = 0.f;

    // ldmatrix base addresses (bytes)
    uint32_t aRow = wr * 64 + (lane & 15);
    uint32_t aCol = (lane >> 4) * 8;
    uint32_t bRow = wc * 32 + (lane & 7);
    uint32_t bCol = (lane >> 3) * 8;

    for (int ch = 0; ch < NKCH; ++ch) {
        int k0 = ch * GBK;
        {
            const uint4* pAh0 = (const uint4*)(Ahi + (size_t)(m0 + r0c) * DD + k0 + c0c);
            const uint4* pAh1 = (const uint4*)(Ahi + (size_t)(m0 + r1c) * DD + k0 + c1c);
            const uint4* pAl0 = (const uint4*)(Alo + (size_t)(m0 + r0c) * DD + k0 + c0c);
            const uint4* pAl1 = (const uint4*)(Alo + (size_t)(m0 + r1c) * DD + k0 + c1c);
            const uint4* pBh0 = (const uint4*)(Bhi + (size_t)(n0 + r0c) * DD + k0 + c0c);
            const uint4* pBh1 = (const uint4*)(Bhi + (size_t)(n0 + r1c) * DD + k0 + c1c);
            const uint4* pBl0 = (const uint4*)(Blo + (size_t)(n0 + r0c) * DD + k0 + c0c);
            const uint4* pBl1 = (const uint4*)(Blo + (size_t)(n0 + r1c) * DD + k0 + c1c);
            *(uint4*)&sAh[r0c * ASTR + c0c] = *pAh0;
            *(uint4*)&sAh[r1c * ASTR + c1c] = *pAh1;
            *(uint4*)&sAl[r0c * ASTR + c0c] = *pAl0;
            *(uint4*)&sAl[r1c * ASTR + c1c] = *pAl1;
            *(uint4*)&sBh[r0c * ASTR + c0c] = *pBh0;
            *(uint4*)&sBh[r1c * ASTR + c1c] = *pBh1;
            *(uint4*)&sBl[r0c * ASTR + c0c] = *pBl0;
            *(uint4*)&sBl[r1c * ASTR + c1c] = *pBl1;
        }
        __syncthreads();

        // B fragments for the whole BK=32 chunk: regs [nt][0..3]
        // x4 matrices: (k0-7),(k8-15),(k16-23),(k24-31) -> ksteps {0,1} use pairs
        uint32_t fbh[4][4], fbl[4][4];
#pragma unroll
        for (int nt = 0; nt < 4; ++nt) {
            uint32_t off = ((bRow + nt * 8) * ASTR + bCol) * 2;
            ldsm_x4(fbh[nt], bBh + off);
            ldsm_x4(fbl[nt], bBl + off);
        }

#pragma unroll
        for (int ks = 0; ks < 2; ++ks) {
            uint32_t fah[4][4], fal[4][4];
#pragma unroll
            for (int mt = 0; mt < 4; ++mt) {
                uint32_t off = ((aRow + mt * 16) * ASTR + ks * 16 + aCol) * 2;
                ldsm_x4(fah[mt], bAh + off);
                ldsm_x4(fal[mt], bAl + off);
            }
#pragma unroll
            for (int mt = 0; mt < 4; ++mt)
#pragma unroll
                for (int nt = 0; nt < 4; ++nt) {
                    uint32_t b0 = fbh[nt][ks * 2], b1 = fbh[nt][ks * 2 + 1];
                    uint32_t c0 = fbl[nt][ks * 2], c1 = fbl[nt][ks * 2 + 1];
                    mma_bf16(acc[mt][nt], fah[mt], b0, b1);   // Ah*Bh
                    mma_bf16(acc[mt][nt], fah[mt], c0, c1);   // Ah*Bl
                    mma_bf16(acc[mt][nt], fal[mt], b0, b1);   // Al*Bh
                }
        }
        __syncthreads();
    }

    // epilogue: d0=(r,c) d1=(r,c+1) d2=(r+8,c) d3=(r+8,c+1); r=lane/4, c=2*(lane%4)
    int erow = m0 + wr * 64 + (lane >> 2);
    int ecol = n0 + wc * 32 + (lane & 3) * 2;
#pragma unroll
    for (int mt = 0; mt < 4; ++mt) {
#pragma unroll
        for (int nt = 0; nt < 4; ++nt) {
            float v0 = acc[mt][nt][0], v1 = acc[mt][nt][1];
            float v2 = acc[mt][nt][2], v3 = acc[mt][nt][3];
            if (mode == 1) {
                v0 = (v0 > 0.f) ? (v0 + 1.f) : expf(v0);
                v1 = (v1 > 0.f) ? (v1 + 1.f) : expf(v1);
                v2 = (v2 > 0.f) ? (v2 + 1.f) : expf(v2);
                v3 = (v3 > 0.f) ? (v3 + 1.f) : expf(v3);
            }
            float* p0 = C + (size_t)(erow + mt * 16) * DD + ecol + nt * 8;
            float* p1 = C + (size_t)(erow + mt * 16 + 8) * DD + ecol + nt * 8;
            *(float2*)p0 = make_float2(v0, v1);
            *(float2*)p1 = make_float2(v2, v3);
        }
    }
}

// ---------------------------------------------------------------------------
// x -> bf16 hi/lo split (elementwise)
// ---------------------------------------------------------------------------
__global__ __launch_bounds__(256) void convert_x(const float* __restrict__ x,
                                                 __nv_bfloat16* __restrict__ hi,
                                                 __nv_bfloat16* __restrict__ lo) {
    size_t i4 = ((size_t)blockIdx.x * 256 + threadIdx.x) * 4;
    float4 v = *(const float4*)(x + i4);
    __nv_bfloat16 h0 = __float2bfloat16(v.x), h1 = __float2bfloat16(v.y);
    __nv_bfloat16 h2 = __float2bfloat16(v.z), h3 = __float2bfloat16(v.w);
    __nv_bfloat16 l0 = __float2bfloat16(v.x - __bfloat162float(h0));
    __nv_bfloat16 l1 = __float2bfloat16(v.y - __bfloat162float(h1));
    __nv_bfloat16 l2 = __float2bfloat16(v.z - __bfloat162float(h2));
    __nv_bfloat16 l3 = __float2bfloat16(v.w - __bfloat162float(h3));
    __nv_bfloat162 ph0; ph0.x = h0; ph0.y = h1;
    __nv_bfloat162 ph1; ph1.x = h2; ph1.y = h3;
    __nv_bfloat162 pl0; pl0.x = l0; pl0.y = l1;
    __nv_bfloat162 pl1; pl1.x = l2; pl1.y = l3;
    *(__nv_bfloat162*)(hi + i4)     = ph0;
    *(__nv_bfloat162*)(hi + i4 + 2) = ph1;
    *(__nv_bfloat162*)(lo + i4)     = pl0;
    *(__nv_bfloat162*)(lo + i4 + 2) = pl1;
}

// ---------------------------------------------------------------------------
// W [K,N] fp32 -> Wt [N,K] bf16 hi/lo (transpose + split)
// ---------------------------------------------------------------------------
__global__ __launch_bounds__(256) void wconv(const float* __restrict__ W,
                                             __nv_bfloat16* __restrict__ Whi,
                                             __nv_bfloat16* __restrict__ Wlo) {
    __shared__ float ts[32][33];
    int n0 = blockIdx.x * 32, k0 = blockIdx.y * 32;
    int tx = threadIdx.x, ty = threadIdx.y;
#pragma unroll
    for (int j = 0; j < 4; ++j)
        ts[ty + j * 8][tx] = W[(size_t)(k0 + ty + j * 8) * DD + n0 + tx];
    __syncthreads();
#pragma unroll
    for (int j = 0; j < 4; ++j) {
        float v = ts[tx][ty + j * 8];
        __nv_bfloat16 h = __float2bfloat16(v);
        __nv_bfloat16 l = __float2bfloat16(v - __bfloat162float(h));
        size_t o = (size_t)(n0 + ty + j * 8) * DD + k0 + tx;
        Whi[o] = h;
        Wlo[o] = l;
    }
}

// ---------------------------------------------------------------------------
// Per-chunk sums: cS[bid] = K_chunk^T @ V_chunk (64x64), cz[bid] = colsum(K)
// ---------------------------------------------------------------------------
__global__ __launch_bounds__(256) void chunk_sums(const float* __restrict__ k,
                                                  const float* __restrict__ v,
                                                  float* __restrict__ cS,
                                                  float* __restrict__ cz) {
    __shared__ float Ks[64 * 64];
    __shared__ float Vs[64 * 64];

    int bid = blockIdx.x;
    int bh  = bid >> 6;
    int c   = bid & 63;
    int b   = bh >> 4;
    int tid = threadIdx.x;

    size_t gbase = ((size_t)(b * SS + c * CC)) * DD + (size_t)(bh & 15) * DH;
    for (int t4 = tid; t4 < 1024; t4 += 256) {
        int row = t4 >> 4;
        int c4  = (t4 & 15) * 4;
        *(float4*)&Ks[row * 64 + c4] = *(const float4*)&k[gbase + (size_t)row * DD + c4];
        *(float4*)&Vs[row * 64 + c4] = *(const float4*)&v[gbase + (size_t)row * DD + c4];
    }
    __syncthreads();

    int d  = tid >> 2;
    int eb = (tid & 3) * 16;
    float acc[16];
#pragma unroll
    for (int ee = 0; ee < 16; ++ee) acc[ee] = 0.f;

    for (int t = 0; t < 64; ++t) {
        float kd = Ks[t * 64 + d];
        const float4* vr = (const float4*)&Vs[t * 64 + eb];
        float4 v0 = vr[0], v1 = vr[1], v2 = vr[2], v3 = vr[3];
        acc[0]  += kd * v0.x; acc[1]  += kd * v0.y; acc[2]  += kd * v0.z; acc[3]  += kd * v0.w;
        acc[4]  += kd * v1.x; acc[5]  += kd * v1.y; acc[6]  += kd * v1.z; acc[7]  += kd * v1.w;
        acc[8]  += kd * v2.x; acc[9]  += kd * v2.y; acc[10] += kd * v2.z; acc[11] += kd * v2.w;
        acc[12] += kd * v3.x; acc[13] += kd * v3.y; acc[14] += kd * v3.z; acc[15] += kd * v3.w;
    }
    float* out = cS + (size_t)bid * 4096 + d * 64 + eb;
#pragma unroll
    for (int e4 = 0; e4 < 4; ++e4)
        *(float4*)&out[e4 * 4] = make_float4(acc[e4 * 4], acc[e4 * 4 + 1],
                                             acc[e4 * 4 + 2], acc[e4 * 4 + 3]);

    if (tid < 64) {
        float zsum = 0.f;
        for (int t = 0; t < 64; ++t) zsum += Ks[t * 64 + tid];
        cz[(size_t)bid * 64 + tid] = zsum;
    }
}

// ---------------------------------------------------------------------------
// Exclusive prefix over chunks, seeded with state_cache.
// ---------------------------------------------------------------------------
__global__ __launch_bounds__(256) void prefix_kernel(const float* __restrict__ cache,
                                                     float* __restrict__ cS,
                                                     float* __restrict__ cz) {
    int bh  = blockIdx.x;
    int tid = threadIdx.x;

    float run[16];
    {
        int f0 = tid * 16;
#pragma unroll
        for (int u = 0; u < 16; ++u) {
            int f = f0 + u;
            int d = f >> 6, e = f & 63;
            run[u] = cache[((size_t)bh * 65 + d) * 64 + e];
        }
    }
    float runz = (tid < 64) ? cache[((size_t)bh * 65 + 64) * 64 + tid] : 0.f;

    for (int c = 0; c < NC; ++c) {
        size_t base = ((size_t)(bh * NC + c)) * 4096 + (size_t)tid * 16;
#pragma unroll
        for (int u = 0; u < 16; ++u) {
            float t = cS[base + u];
            cS[base + u] = run[u];
            run[u] += t;
        }
        if (tid < 64) {
            size_t zb = ((size_t)(bh * NC + c)) * 64 + tid;
            float t = cz[zb];
            cz[zb] = runz;
            runz += t;
        }
    }
}

// ---------------------------------------------------------------------------
// Intra-chunk causal attention + inter-chunk state application.
// Writes bf16 hi/lo activations for the Wo GEMM.
// ---------------------------------------------------------------------------
#define PSTR 68
#define SMEM_INTRA ((5 * 64 * PSTR + 64) * 4)

__global__ __launch_bounds__(256) void intra_kernel(const float* __restrict__ q,
                                                    const float* __restrict__ k,
                                                    const float* __restrict__ v,
                                                    const float* __restrict__ cS,
                                                    const float* __restrict__ cz,
                                                    __nv_bfloat16* __restrict__ ahi,
                                                    __nv_bfloat16* __restrict__ alo) {
    extern __shared__ float sm[];
    float* Qs = sm;
    float* Ks = sm + 64 * PSTR;
    float* Vs = sm + 2 * 64 * PSTR;
    float* Ss = sm + 3 * 64 * PSTR;
    float* As = sm + 4 * 64 * PSTR;
    float* zs = sm + 5 * 64 * PSTR;

    int bid = blockIdx.x;
    int bh  = bid >> 6;
    int c   = bid & 63;
    int b   = bh >> 4;
    int tid = threadIdx.x;

    size_t gbase = ((size_t)(b * SS + c * CC)) * DD + (size_t)(bh & 15) * DH;
    for (int t4 = tid; t4 < 1024; t4 += 256) {
        int row = t4 >> 4;
        int c4  = (t4 & 15) * 4;
        size_t go = gbase + (size_t)row * DD + c4;
        *(float4*)&Qs[row * PSTR + c4] = *(const float4*)&q[go];
        *(float4*)&Ks[row * PSTR + c4] = *(const float4*)&k[go];
        *(float4*)&Vs[row * PSTR + c4] = *(const float4*)&v[go];
        *(float4*)&Ss[row * PSTR + c4] = *(const float4*)&cS[(size_t)bid * 4096 + (size_t)t4 * 4];
    }
    if (tid < 64) zs[tid] = cz[(size_t)bid * 64 + tid];
    __syncthreads();

    int i  = tid >> 2;
    int q4 = tid & 3;
    int eb = q4 * 16;
    const float* qrow = &Qs[i * PSTR];

    // Phase A: masked A row strip + den (strided j = jj*4+q4)
    float ap[16];
#pragma unroll
    for (int jj = 0; jj < 16; ++jj) ap[jj] = 0.f;
    for (int d = 0; d < 64; ++d) {
        float qd = qrow[d];
#pragma unroll
        for (int jj = 0; jj < 16; ++jj)
            ap[jj] += qd * Ks[(jj * 4 + q4) * PSTR + d];
    }
    float den = 0.f;
#pragma unroll
    for (int jj = 0; jj < 16; ++jj) {
        int j = jj * 4 + q4;
        if (j > i) ap[jj] = 0.f;
        As[i * PSTR + j] = ap[jj];
        den += ap[jj];
    }
#pragma unroll
    for (int dd = 0; dd < 16; ++dd) {
        int d = dd * 4 + q4;
        den += qrow[d] * zs[d];
    }
    den += __shfl_xor_sync(0xffffffffu, den, 1);
    den += __shfl_xor_sync(0xffffffffu, den, 2);
    float inv = 1.f / (den + EPS);
    __syncthreads();

    // Phase B: num = Q @ S_start + A @ V   (contiguous e = eb..eb+15, float4)
    float num[16];
#pragma unroll
    for (int ee = 0; ee < 16; ++ee) num[ee] = 0.f;
    for (int d = 0; d < 64; ++d) {
        float qd = qrow[d];
        const float4* sr = (const float4*)&Ss[d * PSTR + eb];
        float4 s0 = sr[0], s1 = sr[1], s2 = sr[2], s3 = sr[3];
        num[0]  += qd * s0.x; num[1]  += qd * s0.y; num[2]  += qd * s0.z; num[3]  += qd * s0.w;
        num[4]  += qd * s1.x; num[5]  += qd * s1.y; num[6]  += qd * s1.z; num[7]  += qd * s1.w;
        num[8]  += qd * s2.x; num[9]  += qd * s2.y; num[10] += qd * s2.z; num[11] += qd * s2.w;
        num[12] += qd * s3.x; num[13] += qd * s3.y; num[14] += qd * s3.z; num[15] += qd * s3.w;
    }
    for (int j = 0; j < 64; ++j) {
        float aij = As[i * PSTR + j];
        const float4* vr = (const float4*)&Vs[j * PSTR + eb];
        float4 v0 = vr[0], v1 = vr[1], v2 = vr[2], v3 = vr[3];
        num[0]  += aij * v0.x; num[1]  += aij * v0.y; num[2]  += aij * v0.z; num[3]  += aij * v0.w;
        num[4]  += aij * v1.x; num[5]  += aij * v1.y; num[6]  += aij * v1.z; num[7]  += aij * v1.w;
        num[8]  += aij * v2.x; num[9]  += aij * v2.y; num[10] += aij * v2.z; num[11] += aij * v2.w;
        num[12] += aij * v3.x; num[13] += aij * v3.y; num[14] += aij * v3.z; num[15] += aij * v3.w;
    }

    size_t obase = gbase + (size_t)i * DD + eb;
#pragma unroll
    for (int ee = 0; ee < 16; ++ee) {
        float r = num[ee] * inv;
        __nv_bfloat16 h = __float2bfloat16(r);
        __nv_bfloat16 l = __float2bfloat16(r - __bfloat162float(h));
        ahi[obase + ee] = h;
        alo[obase + ee] = l;
    }
}

// ---------------------------------------------------------------------------
// Launch
// ---------------------------------------------------------------------------
extern "C" void kernel_launch(void* const* d_in, const int* in_sizes, int n_in,
                              void* d_out, int out_size) {
    const float* x     = (const float*)d_in[0];
    const float* cache = (const float*)d_in[1];
    const float* Wq    = (const float*)d_in[2];
    const float* Wk    = (const float*)d_in[3];
    const float* Wv    = (const float*)d_in[4];
    const float* Wo    = (const float*)d_in[5];
    float* out = (float*)d_out;

    float *qp, *kp, *vp, *cSp, *czp;
    __nv_bfloat16 *xhi, *xlo, *ahi, *alo, *wthi, *wtlo;
    cudaGetSymbolAddress((void**)&qp,   g_q);
    cudaGetSymbolAddress((void**)&kp,   g_k);
    cudaGetSymbolAddress((void**)&vp,   g_v);
    cudaGetSymbolAddress((void**)&cSp,  g_cS);
    cudaGetSymbolAddress((void**)&czp,  g_cz);
    cudaGetSymbolAddress((void**)&xhi,  g_xhi);
    cudaGetSymbolAddress((void**)&xlo,  g_xlo);
    cudaGetSymbolAddress((void**)&ahi,  g_ahi);
    cudaGetSymbolAddress((void**)&alo,  g_alo);
    cudaGetSymbolAddress((void**)&wthi, g_wthi);
    cudaGetSymbolAddress((void**)&wtlo, g_wtlo);

    cudaFuncSetAttribute(intra_kernel, cudaFuncAttributeMaxDynamicSharedMemorySize,
                         SMEM_INTRA);

    const size_t WSTRIDE = (size_t)DD * DD;

    convert_x<<<MM * DD / 1024, 256>>>(x, xhi, xlo);
    wconv<<<dim3(32, 32), dim3(32, 8)>>>(Wq, wthi + 0 * WSTRIDE, wtlo + 0 * WSTRIDE);
    wconv<<<dim3(32, 32), dim3(32, 8)>>>(Wk, wthi + 1 * WSTRIDE, wtlo + 1 * WSTRIDE);
    wconv<<<dim3(32, 32), dim3(32, 8)>>>(Wv, wthi + 2 * WSTRIDE, wtlo + 2 * WSTRIDE);
    wconv<<<dim3(32, 32), dim3(32, 8)>>>(Wo, wthi + 3 * WSTRIDE, wtlo + 3 * WSTRIDE);

    dim3 gg(DD / 128, MM / 128);  // (8, 128)
    gemm_mma<<<gg, 256>>>(xhi, xlo, wthi + 0 * WSTRIDE, wtlo + 0 * WSTRIDE, qp, 1);
    gemm_mma<<<gg, 256>>>(xhi, xlo, wthi + 1 * WSTRIDE, wtlo + 1 * WSTRIDE, kp, 1);
    gemm_mma<<<gg, 256>>>(xhi, xlo, wthi + 2 * WSTRIDE, wtlo + 2 * WSTRIDE, vp, 0);

    chunk_sums<<<BB * HH * NC, 256>>>(kp, vp, cSp, czp);
    prefix_kernel<<<BB * HH, 256>>>(cache, cSp, czp);
    intra_kernel<<<BB * HH * NC, 256, SMEM_INTRA>>>(qp, kp, vp, cSp, czp, ahi, alo);

    gemm_mma<<<gg, 256>>>(ahi, alo, wthi + 3 * WSTRIDE, wtlo + 3 * WSTRIDE, out, 0);
}

// round 10
// speedup vs baseline: 1.5014x; 1.1748x over previous
#include <cuda_runtime.h>
#include <cuda_bf16.h>
#include <math.h>
#include <cstdint>

// Problem constants
#define BB 4
#define SS 4096
#define DD 1024
#define HH 16
#define DH 64
#define MM (BB * SS)          // 16384 rows
#define CC 64                 // chunk length
#define NC (SS / CC)          // 64 chunks per sequence
#define EPS 1e-6f

// ---------------------------------------------------------------------------
// Scratch (device globals; no allocation allowed)
// ---------------------------------------------------------------------------
__device__ __align__(256) float g_q[(size_t)MM * DD];
__device__ __align__(256) float g_k[(size_t)MM * DD];
__device__ __align__(256) float g_v[(size_t)MM * DD];
__device__ __align__(256) __nv_bfloat16 g_xhi[(size_t)MM * DD];
__device__ __align__(256) __nv_bfloat16 g_xlo[(size_t)MM * DD];
__device__ __align__(256) __nv_bfloat16 g_ahi[(size_t)MM * DD];
__device__ __align__(256) __nv_bfloat16 g_alo[(size_t)MM * DD];
// transposed weights [N,K] bf16, hi/lo, 4 weights (q,k,v,o) -- q,k,v contiguous
__device__ __align__(256) __nv_bfloat16 g_wthi[4][(size_t)DD * DD];
__device__ __align__(256) __nv_bfloat16 g_wtlo[4][(size_t)DD * DD];
// chunk states: [B*H][NC][DH][DH]
__device__ __align__(256) float g_cS[(size_t)BB * HH * NC * DH * DH];
__device__ __align__(256) float g_cz[(size_t)BB * HH * NC * DH];

// ---------------------------------------------------------------------------
// Warp-MMA + cp.async helpers (sm_80-era PTX; assembles for sm_103)
// ---------------------------------------------------------------------------
__device__ __forceinline__ uint32_t smem_u32(const void* p) {
    uint32_t a;
    asm("{ .reg .u64 t; cvta.to.shared.u64 t, %1; cvt.u32.u64 %0, t; }"
        : "=r"(a) : "l"(p));
    return a;
}
__device__ __forceinline__ void ldsm_x4(uint32_t* r, uint32_t addr) {
    asm volatile("ldmatrix.sync.aligned.m8n8.x4.shared.b16 {%0,%1,%2,%3}, [%4];"
                 : "=r"(r[0]), "=r"(r[1]), "=r"(r[2]), "=r"(r[3]) : "r"(addr));
}
__device__ __forceinline__ void mma_bf16(float* d, const uint32_t* a,
                                         uint32_t b0, uint32_t b1) {
    asm volatile(
        "mma.sync.aligned.m16n8k16.row.col.f32.bf16.bf16.f32 "
        "{%0,%1,%2,%3}, {%4,%5,%6,%7}, {%8,%9}, {%0,%1,%2,%3};"
        : "+f"(d[0]), "+f"(d[1]), "+f"(d[2]), "+f"(d[3])
        : "r"(a[0]), "r"(a[1]), "r"(a[2]), "r"(a[3]), "r"(b0), "r"(b1));
}
__device__ __forceinline__ void cpa16(uint32_t dst, const void* src) {
    asm volatile("cp.async.cg.shared.global [%0], [%1], 16;"
                 :: "r"(dst), "l"(src));
}
#define CP_COMMIT() asm volatile("cp.async.commit_group;" ::: "memory")
#define CP_WAIT1()  asm volatile("cp.async.wait_group 1;" ::: "memory")

// ---------------------------------------------------------------------------
// Pipelined mma.sync bf16 GEMM with hi/lo split (3 accumulating passes):
// C[:,n] = (Ahi+Alo)[M,K] @ (Bhi+Blo)[Ntot,K]^T, fp32 out.
// CTA 128x128, BK=32, 8 warps (2x4), warp tile 64x32.
// 2-stage cp.async double buffering. grid.x spans Ntot/128 tiles; tile
// group `which = n0>>10` selects output pointer; phimask bit -> elu+1.
// ---------------------------------------------------------------------------
#define GBK 32
#define NKCH (DD / GBK)       // 32
#define ASTR 40               // padded smem row stride (bf16) - conflict-free
#define STG (128 * ASTR)      // elems per tile buffer
#define GEMM_SMEM (2 * 4 * STG * 2)   // 2 stages x 4 tiles x STG bf16 = 81920 B

__global__ __launch_bounds__(256, 1) void gemm_mma(const __nv_bfloat16* __restrict__ Ahi,
                                                   const __nv_bfloat16* __restrict__ Alo,
                                                   const __nv_bfloat16* __restrict__ Bhi,
                                                   const __nv_bfloat16* __restrict__ Blo,
                                                   float* __restrict__ c0,
                                                   float* __restrict__ c1,
                                                   float* __restrict__ c2,
                                                   int phimask) {
    extern __shared__ __nv_bfloat16 smbuf[];
    uint32_t bsm = smem_u32(smbuf);

    int tid  = threadIdx.x;
    int wid  = tid >> 5;
    int lane = tid & 31;
    int wr   = wid >> 2;      // 0..1  (M, 64 rows)
    int wc   = wid & 3;       // 0..3  (N, 32 cols)
    int m0   = blockIdx.y * 128;
    int n0   = blockIdx.x * 128;

    // per-thread load coords: 2 x 16B per tile per stage
    int r0c = (tid + 0)   >> 2, c0c = ((tid + 0)   & 3) * 8;
    int r1c = (tid + 256) >> 2, c1c = ((tid + 256) & 3) * 8;
    uint32_t off0 = (uint32_t)(r0c * ASTR + c0c) * 2;
    uint32_t off1 = (uint32_t)(r1c * ASTR + c1c) * 2;

    const __nv_bfloat16* gA0h = Ahi + (size_t)(m0 + r0c) * DD + c0c;
    const __nv_bfloat16* gA1h = Ahi + (size_t)(m0 + r1c) * DD + c1c;
    const __nv_bfloat16* gA0l = Alo + (size_t)(m0 + r0c) * DD + c0c;
    const __nv_bfloat16* gA1l = Alo + (size_t)(m0 + r1c) * DD + c1c;
    const __nv_bfloat16* gB0h = Bhi + (size_t)(n0 + r0c) * DD + c0c;
    const __nv_bfloat16* gB1h = Bhi + (size_t)(n0 + r1c) * DD + c1c;
    const __nv_bfloat16* gB0l = Blo + (size_t)(n0 + r0c) * DD + c0c;
    const __nv_bfloat16* gB1l = Blo + (size_t)(n0 + r1c) * DD + c1c;

    auto issue = [&](int ch, int s) {
        int k0 = ch * GBK;
        uint32_t base = bsm + (uint32_t)(s * 4) * (uint32_t)(STG * 2);
        cpa16(base + 0 * STG * 2 + off0, gA0h + k0);
        cpa16(base + 0 * STG * 2 + off1, gA1h + k0);
        cpa16(base + 1 * STG * 2 + off0, gA0l + k0);
        cpa16(base + 1 * STG * 2 + off1, gA1l + k0);
        cpa16(base + 2 * STG * 2 + off0, gB0h + k0);
        cpa16(base + 2 * STG * 2 + off1, gB1h + k0);
        cpa16(base + 3 * STG * 2 + off0, gB0l + k0);
        cpa16(base + 3 * STG * 2 + off1, gB1l + k0);
    };

    float acc[4][4][4];
#pragma unroll
    for (int i = 0; i < 4; ++i)
#pragma unroll
        for (int j = 0; j < 4; ++j)
#pragma unroll
            for (int r = 0; r < 4; ++r) acc[i][j][r] = 0.f;

    // ldmatrix base coords
    uint32_t aRow = wr * 64 + (lane & 15);
    uint32_t aCol = (lane >> 4) * 8;
    uint32_t bRow = wc * 32 + (lane & 7);
    uint32_t bCol = (lane >> 3) * 8;

    issue(0, 0); CP_COMMIT();
    issue(1, 1); CP_COMMIT();

    int cur = 0;
    for (int ch = 0; ch < NKCH; ++ch) {
        CP_WAIT1();
        __syncthreads();

        uint32_t base = bsm + (uint32_t)(cur * 4) * (uint32_t)(STG * 2);
        uint32_t bAh = base, bAl = base + STG * 2;
        uint32_t bBh = base + 2 * STG * 2, bBl = base + 3 * STG * 2;

        // B fragments for the whole BK=32 chunk
        uint32_t fbh[4][4], fbl[4][4];
#pragma unroll
        for (int nt = 0; nt < 4; ++nt) {
            uint32_t off = ((bRow + nt * 8) * ASTR + bCol) * 2;
            ldsm_x4(fbh[nt], bBh + off);
            ldsm_x4(fbl[nt], bBl + off);
        }
#pragma unroll
        for (int ks = 0; ks < 2; ++ks) {
            uint32_t fah[4][4], fal[4][4];
#pragma unroll
            for (int mt = 0; mt < 4; ++mt) {
                uint32_t off = ((aRow + mt * 16) * ASTR + ks * 16 + aCol) * 2;
                ldsm_x4(fah[mt], bAh + off);
                ldsm_x4(fal[mt], bAl + off);
            }
#pragma unroll
            for (int mt = 0; mt < 4; ++mt)
#pragma unroll
                for (int nt = 0; nt < 4; ++nt) {
                    uint32_t b0 = fbh[nt][ks * 2], b1 = fbh[nt][ks * 2 + 1];
                    uint32_t c0r = fbl[nt][ks * 2], c1r = fbl[nt][ks * 2 + 1];
                    mma_bf16(acc[mt][nt], fah[mt], b0, b1);    // Ah*Bh
                    mma_bf16(acc[mt][nt], fah[mt], c0r, c1r);  // Ah*Bl
                    mma_bf16(acc[mt][nt], fal[mt], b0, b1);    // Al*Bh
                }
        }
        __syncthreads();
        if (ch + 2 < NKCH) issue(ch + 2, cur);
        CP_COMMIT();
        cur ^= 1;
    }

    // epilogue
    int which = n0 >> 10;
    float* C  = (which == 0) ? c0 : ((which == 1) ? c1 : c2);
    int mode  = (phimask >> which) & 1;
    int ncol  = n0 & 1023;
    int erow  = m0 + wr * 64 + (lane >> 2);
    int ecol  = ncol + wc * 32 + (lane & 3) * 2;
#pragma unroll
    for (int mt = 0; mt < 4; ++mt) {
#pragma unroll
        for (int nt = 0; nt < 4; ++nt) {
            float v0 = acc[mt][nt][0], v1 = acc[mt][nt][1];
            float v2 = acc[mt][nt][2], v3 = acc[mt][nt][3];
            if (mode) {
                v0 = (v0 > 0.f) ? (v0 + 1.f) : expf(v0);
                v1 = (v1 > 0.f) ? (v1 + 1.f) : expf(v1);
                v2 = (v2 > 0.f) ? (v2 + 1.f) : expf(v2);
                v3 = (v3 > 0.f) ? (v3 + 1.f) : expf(v3);
            }
            float* p0 = C + (size_t)(erow + mt * 16) * DD + ecol + nt * 8;
            float* p1 = C + (size_t)(erow + mt * 16 + 8) * DD + ecol + nt * 8;
            *(float2*)p0 = make_float2(v0, v1);
            *(float2*)p1 = make_float2(v2, v3);
        }
    }
}

// ---------------------------------------------------------------------------
// x -> bf16 hi/lo split (elementwise)
// ---------------------------------------------------------------------------
__global__ __launch_bounds__(256) void convert_x(const float* __restrict__ x,
                                                 __nv_bfloat16* __restrict__ hi,
                                                 __nv_bfloat16* __restrict__ lo) {
    size_t i4 = ((size_t)blockIdx.x * 256 + threadIdx.x) * 4;
    float4 v = *(const float4*)(x + i4);
    __nv_bfloat16 h0 = __float2bfloat16(v.x), h1 = __float2bfloat16(v.y);
    __nv_bfloat16 h2 = __float2bfloat16(v.z), h3 = __float2bfloat16(v.w);
    __nv_bfloat16 l0 = __float2bfloat16(v.x - __bfloat162float(h0));
    __nv_bfloat16 l1 = __float2bfloat16(v.y - __bfloat162float(h1));
    __nv_bfloat16 l2 = __float2bfloat16(v.z - __bfloat162float(h2));
    __nv_bfloat16 l3 = __float2bfloat16(v.w - __bfloat162float(h3));
    __nv_bfloat162 ph0; ph0.x = h0; ph0.y = h1;
    __nv_bfloat162 ph1; ph1.x = h2; ph1.y = h3;
    __nv_bfloat162 pl0; pl0.x = l0; pl0.y = l1;
    __nv_bfloat162 pl1; pl1.x = l2; pl1.y = l3;
    *(__nv_bfloat162*)(hi + i4)     = ph0;
    *(__nv_bfloat162*)(hi + i4 + 2) = ph1;
    *(__nv_bfloat162*)(lo + i4)     = pl0;
    *(__nv_bfloat162*)(lo + i4 + 2) = pl1;
}

// ---------------------------------------------------------------------------
// W [K,N] fp32 -> Wt [N,K] bf16 hi/lo (transpose + split)
// ---------------------------------------------------------------------------
__global__ __launch_bounds__(256) void wconv(const float* __restrict__ W,
                                             __nv_bfloat16* __restrict__ Whi,
                                             __nv_bfloat16* __restrict__ Wlo) {
    __shared__ float ts[32][33];
    int n0 = blockIdx.x * 32, k0 = blockIdx.y * 32;
    int tx = threadIdx.x, ty = threadIdx.y;
#pragma unroll
    for (int j = 0; j < 4; ++j)
        ts[ty + j * 8][tx] = W[(size_t)(k0 + ty + j * 8) * DD + n0 + tx];
    __syncthreads();
#pragma unroll
    for (int j = 0; j < 4; ++j) {
        float v = ts[tx][ty + j * 8];
        __nv_bfloat16 h = __float2bfloat16(v);
        __nv_bfloat16 l = __float2bfloat16(v - __bfloat162float(h));
        size_t o = (size_t)(n0 + ty + j * 8) * DD + k0 + tx;
        Whi[o] = h;
        Wlo[o] = l;
    }
}

// ---------------------------------------------------------------------------
// Per-chunk sums: cS[bid] = K_chunk^T @ V_chunk (64x64), cz[bid] = colsum(K)
// ---------------------------------------------------------------------------
__global__ __launch_bounds__(256) void chunk_sums(const float* __restrict__ k,
                                                  const float* __restrict__ v,
                                                  float* __restrict__ cS,
                                                  float* __restrict__ cz) {
    __shared__ float Ks[64 * 64];
    __shared__ float Vs[64 * 64];

    int bid = blockIdx.x;
    int bh  = bid >> 6;
    int c   = bid & 63;
    int b   = bh >> 4;
    int tid = threadIdx.x;

    size_t gbase = ((size_t)(b * SS + c * CC)) * DD + (size_t)(bh & 15) * DH;
    for (int t4 = tid; t4 < 1024; t4 += 256) {
        int row = t4 >> 4;
        int c4  = (t4 & 15) * 4;
        *(float4*)&Ks[row * 64 + c4] = *(const float4*)&k[gbase + (size_t)row * DD + c4];
        *(float4*)&Vs[row * 64 + c4] = *(const float4*)&v[gbase + (size_t)row * DD + c4];
    }
    __syncthreads();

    int d  = tid >> 2;
    int eb = (tid & 3) * 16;
    float acc[16];
#pragma unroll
    for (int ee = 0; ee < 16; ++ee) acc[ee] = 0.f;

    for (int t = 0; t < 64; ++t) {
        float kd = Ks[t * 64 + d];
        const float4* vr = (const float4*)&Vs[t * 64 + eb];
        float4 v0 = vr[0], v1 = vr[1], v2 = vr[2], v3 = vr[3];
        acc[0]  += kd * v0.x; acc[1]  += kd * v0.y; acc[2]  += kd * v0.z; acc[3]  += kd * v0.w;
        acc[4]  += kd * v1.x; acc[5]  += kd * v1.y; acc[6]  += kd * v1.z; acc[7]  += kd * v1.w;
        acc[8]  += kd * v2.x; acc[9]  += kd * v2.y; acc[10] += kd * v2.z; acc[11] += kd * v2.w;
        acc[12] += kd * v3.x; acc[13] += kd * v3.y; acc[14] += kd * v3.z; acc[15] += kd * v3.w;
    }
    float* out = cS + (size_t)bid * 4096 + d * 64 + eb;
#pragma unroll
    for (int e4 = 0; e4 < 4; ++e4)
        *(float4*)&out[e4 * 4] = make_float4(acc[e4 * 4], acc[e4 * 4 + 1],
                                             acc[e4 * 4 + 2], acc[e4 * 4 + 3]);

    if (tid < 64) {
        float zsum = 0.f;
        for (int t = 0; t < 64; ++t) zsum += Ks[t * 64 + tid];
        cz[(size_t)bid * 64 + tid] = zsum;
    }
}

// ---------------------------------------------------------------------------
// Exclusive prefix over chunks, seeded with state_cache.
// ---------------------------------------------------------------------------
__global__ __launch_bounds__(256) void prefix_kernel(const float* __restrict__ cache,
                                                     float* __restrict__ cS,
                                                     float* __restrict__ cz) {
    int bh  = blockIdx.x;
    int tid = threadIdx.x;

    float run[16];
    {
        int f0 = tid * 16;
#pragma unroll
        for (int u = 0; u < 16; ++u) {
            int f = f0 + u;
            int d = f >> 6, e = f & 63;
            run[u] = cache[((size_t)bh * 65 + d) * 64 + e];
        }
    }
    float runz = (tid < 64) ? cache[((size_t)bh * 65 + 64) * 64 + tid] : 0.f;

    for (int c = 0; c < NC; ++c) {
        size_t base = ((size_t)(bh * NC + c)) * 4096 + (size_t)tid * 16;
#pragma unroll
        for (int u = 0; u < 16; ++u) {
            float t = cS[base + u];
            cS[base + u] = run[u];
            run[u] += t;
        }
        if (tid < 64) {
            size_t zb = ((size_t)(bh * NC + c)) * 64 + tid;
            float t = cz[zb];
            cz[zb] = runz;
            runz += t;
        }
    }
}

// ---------------------------------------------------------------------------
// Intra-chunk causal attention + inter-chunk state application.
// Writes bf16 hi/lo activations for the Wo GEMM.
// ---------------------------------------------------------------------------
#define PSTR 68
#define SMEM_INTRA ((5 * 64 * PSTR + 64) * 4)

__global__ __launch_bounds__(256) void intra_kernel(const float* __restrict__ q,
                                                    const float* __restrict__ k,
                                                    const float* __restrict__ v,
                                                    const float* __restrict__ cS,
                                                    const float* __restrict__ cz,
                                                    __nv_bfloat16* __restrict__ ahi,
                                                    __nv_bfloat16* __restrict__ alo) {
    extern __shared__ float sm[];
    float* Qs = sm;
    float* Ks = sm + 64 * PSTR;
    float* Vs = sm + 2 * 64 * PSTR;
    float* Ss = sm + 3 * 64 * PSTR;
    float* As = sm + 4 * 64 * PSTR;
    float* zs = sm + 5 * 64 * PSTR;

    int bid = blockIdx.x;
    int bh  = bid >> 6;
    int c   = bid & 63;
    int b   = bh >> 4;
    int tid = threadIdx.x;

    size_t gbase = ((size_t)(b * SS + c * CC)) * DD + (size_t)(bh & 15) * DH;
    for (int t4 = tid; t4 < 1024; t4 += 256) {
        int row = t4 >> 4;
        int c4  = (t4 & 15) * 4;
        size_t go = gbase + (size_t)row * DD + c4;
        *(float4*)&Qs[row * PSTR + c4] = *(const float4*)&q[go];
        *(float4*)&Ks[row * PSTR + c4] = *(const float4*)&k[go];
        *(float4*)&Vs[row * PSTR + c4] = *(const float4*)&v[go];
        *(float4*)&Ss[row * PSTR + c4] = *(const float4*)&cS[(size_t)bid * 4096 + (size_t)t4 * 4];
    }
    if (tid < 64) zs[tid] = cz[(size_t)bid * 64 + tid];
    __syncthreads();

    int i  = tid >> 2;
    int q4 = tid & 3;
    int eb = q4 * 16;
    const float* qrow = &Qs[i * PSTR];

    // Phase A: masked A row strip + den (strided j = jj*4+q4)
    float ap[16];
#pragma unroll
    for (int jj = 0; jj < 16; ++jj) ap[jj] = 0.f;
    for (int d = 0; d < 64; ++d) {
        float qd = qrow[d];
#pragma unroll
        for (int jj = 0; jj < 16; ++jj)
            ap[jj] += qd * Ks[(jj * 4 + q4) * PSTR + d];
    }
    float den = 0.f;
#pragma unroll
    for (int jj = 0; jj < 16; ++jj) {
        int j = jj * 4 + q4;
        if (j > i) ap[jj] = 0.f;
        As[i * PSTR + j] = ap[jj];
        den += ap[jj];
    }
#pragma unroll
    for (int dd = 0; dd < 16; ++dd) {
        int d = dd * 4 + q4;
        den += qrow[d] * zs[d];
    }
    den += __shfl_xor_sync(0xffffffffu, den, 1);
    den += __shfl_xor_sync(0xffffffffu, den, 2);
    float inv = 1.f / (den + EPS);
    __syncthreads();

    // Phase B: num = Q @ S_start + A @ V   (contiguous e = eb..eb+15, float4)
    float num[16];
#pragma unroll
    for (int ee = 0; ee < 16; ++ee) num[ee] = 0.f;
    for (int d = 0; d < 64; ++d) {
        float qd = qrow[d];
        const float4* sr = (const float4*)&Ss[d * PSTR + eb];
        float4 s0 = sr[0], s1 = sr[1], s2 = sr[2], s3 = sr[3];
        num[0]  += qd * s0.x; num[1]  += qd * s0.y; num[2]  += qd * s0.z; num[3]  += qd * s0.w;
        num[4]  += qd * s1.x; num[5]  += qd * s1.y; num[6]  += qd * s1.z; num[7]  += qd * s1.w;
        num[8]  += qd * s2.x; num[9]  += qd * s2.y; num[10] += qd * s2.z; num[11] += qd * s2.w;
        num[12] += qd * s3.x; num[13] += qd * s3.y; num[14] += qd * s3.z; num[15] += qd * s3.w;
    }
    for (int j = 0; j < 64; ++j) {
        float aij = As[i * PSTR + j];
        const float4* vr = (const float4*)&Vs[j * PSTR + eb];
        float4 v0 = vr[0], v1 = vr[1], v2 = vr[2], v3 = vr[3];
        num[0]  += aij * v0.x; num[1]  += aij * v0.y; num[2]  += aij * v0.z; num[3]  += aij * v0.w;
        num[4]  += aij * v1.x; num[5]  += aij * v1.y; num[6]  += aij * v1.z; num[7]  += aij * v1.w;
        num[8]  += aij * v2.x; num[9]  += aij * v2.y; num[10] += aij * v2.z; num[11] += aij * v2.w;
        num[12] += aij * v3.x; num[13] += aij * v3.y; num[14] += aij * v3.z; num[15] += aij * v3.w;
    }

    size_t obase = gbase + (size_t)i * DD + eb;
#pragma unroll
    for (int ee = 0; ee < 16; ++ee) {
        float r = num[ee] * inv;
        __nv_bfloat16 h = __float2bfloat16(r);
        __nv_bfloat16 l = __float2bfloat16(r - __bfloat162float(h));
        ahi[obase + ee] = h;
        alo[obase + ee] = l;
    }
}

// ---------------------------------------------------------------------------
// Launch
// ---------------------------------------------------------------------------
extern "C" void kernel_launch(void* const* d_in, const int* in_sizes, int n_in,
                              void* d_out, int out_size) {
    const float* x     = (const float*)d_in[0];
    const float* cache = (const float*)d_in[1];
    const float* Wq    = (const float*)d_in[2];
    const float* Wk    = (const float*)d_in[3];
    const float* Wv    = (const float*)d_in[4];
    const float* Wo    = (const float*)d_in[5];
    float* out = (float*)d_out;

    float *qp, *kp, *vp, *cSp, *czp;
    __nv_bfloat16 *xhi, *xlo, *ahi, *alo, *wthi, *wtlo;
    cudaGetSymbolAddress((void**)&qp,   g_q);
    cudaGetSymbolAddress((void**)&kp,   g_k);
    cudaGetSymbolAddress((void**)&vp,   g_v);
    cudaGetSymbolAddress((void**)&cSp,  g_cS);
    cudaGetSymbolAddress((void**)&czp,  g_cz);
    cudaGetSymbolAddress((void**)&xhi,  g_xhi);
    cudaGetSymbolAddress((void**)&xlo,  g_xlo);
    cudaGetSymbolAddress((void**)&ahi,  g_ahi);
    cudaGetSymbolAddress((void**)&alo,  g_alo);
    cudaGetSymbolAddress((void**)&wthi, g_wthi);
    cudaGetSymbolAddress((void**)&wtlo, g_wtlo);

    cudaFuncSetAttribute(intra_kernel, cudaFuncAttributeMaxDynamicSharedMemorySize,
                         SMEM_INTRA);
    cudaFuncSetAttribute(gemm_mma, cudaFuncAttributeMaxDynamicSharedMemorySize,
                         GEMM_SMEM);

    const size_t WSTRIDE = (size_t)DD * DD;

    convert_x<<<MM * DD / 1024, 256>>>(x, xhi, xlo);
    wconv<<<dim3(32, 32), dim3(32, 8)>>>(Wq, wthi + 0 * WSTRIDE, wtlo + 0 * WSTRIDE);
    wconv<<<dim3(32, 32), dim3(32, 8)>>>(Wk, wthi + 1 * WSTRIDE, wtlo + 1 * WSTRIDE);
    wconv<<<dim3(32, 32), dim3(32, 8)>>>(Wv, wthi + 2 * WSTRIDE, wtlo + 2 * WSTRIDE);
    wconv<<<dim3(32, 32), dim3(32, 8)>>>(Wo, wthi + 3 * WSTRIDE, wtlo + 3 * WSTRIDE);

    // Fused QKV GEMM: B rows span concatenated [Wq^T | Wk^T | Wv^T] (3072 rows)
    gemm_mma<<<dim3(24, 128), 256, GEMM_SMEM>>>(xhi, xlo, wthi, wtlo,
                                                qp, kp, vp, 0b011);

    chunk_sums<<<BB * HH * NC, 256>>>(kp, vp, cSp, czp);
    prefix_kernel<<<BB * HH, 256>>>(cache, cSp, czp);
    intra_kernel<<<BB * HH * NC, 256, SMEM_INTRA>>>(qp, kp, vp, cSp, czp, ahi, alo);

    // Wo GEMM
    gemm_mma<<<dim3(8, 128), 256, GEMM_SMEM>>>(ahi, alo,
                                               wthi + 3 * WSTRIDE, wtlo + 3 * WSTRIDE,
                                               out, out, out, 0);
}